// round 2
// baseline (speedup 1.0000x reference)
#include <cuda_runtime.h>
#include <cuda_bf16.h>

// Problem constants (shapes fixed by the dataset)
#define DIMV 128
#define NTYPES 32
#define MAXV 50048
#define MAXVP 53248          // 13 * 4096, padded for the scan
#define MAXE 650000

// Scratch (device globals; no allocation allowed)
__device__ float g_src_proj[(size_t)MAXV * DIMV];
__device__ float g_dest_proj[(size_t)MAXV * DIMV];
__device__ int   g_cnt[MAXVP];
__device__ int   g_starts[MAXVP];
__device__ int   g_cursor[MAXVP];
__device__ int   g_bsum[16];
__device__ int2  g_srccls[MAXE];   // (src, cls) sorted by dest

// ---------------------------------------------------------------------------
// Zero the histogram counters
// ---------------------------------------------------------------------------
__global__ void zero_cnt_kernel() {
    int i = blockIdx.x * blockDim.x + threadIdx.x;
    if (i < MAXVP) g_cnt[i] = 0;
}

// ---------------------------------------------------------------------------
// Histogram of edge destinations
// ---------------------------------------------------------------------------
__global__ void hist_kernel(const int* __restrict__ edst, int E) {
    int i = blockIdx.x * blockDim.x + threadIdx.x;
    if (i < E) atomicAdd(&g_cnt[edst[i]], 1);
}

// ---------------------------------------------------------------------------
// 3-phase exclusive scan over g_cnt[MAXVP] -> g_starts, g_cursor
// Phase 1: per-block (4096 elems, 512 thr x 8) local exclusive scan + block sum
// ---------------------------------------------------------------------------
#define SCAN_BLK 512
#define SCAN_EPB 4096
#define SCAN_NB  (MAXVP / SCAN_EPB)   // 13

__global__ __launch_bounds__(SCAN_BLK) void scan1_kernel() {
    __shared__ int wsum[16];
    const int b = blockIdx.x, t = threadIdx.x;
    const int base = b * SCAN_EPB + t * 8;
    int v[8];
#pragma unroll
    for (int i = 0; i < 8; i++) v[i] = g_cnt[base + i];
    int run = 0;
#pragma unroll
    for (int i = 0; i < 8; i++) { int tmp = v[i]; v[i] = run; run += tmp; }
    // warp exclusive scan of per-thread totals
    int lane = t & 31, wid = t >> 5;
    int incl = run;
#pragma unroll
    for (int o = 1; o < 32; o <<= 1) {
        int n = __shfl_up_sync(0xffffffffu, incl, o);
        if (lane >= o) incl += n;
    }
    if (lane == 31) wsum[wid] = incl;
    __syncthreads();
    if (wid == 0) {
        int ws = (lane < 16) ? wsum[lane] : 0;
#pragma unroll
        for (int o = 1; o < 16; o <<= 1) {
            int n = __shfl_up_sync(0xffffffffu, ws, o);
            if (lane >= o) ws += n;
        }
        if (lane < 16) wsum[lane] = ws;            // inclusive warp sums
        if (lane == 15) g_bsum[b] = ws;            // block total
    }
    __syncthreads();
    int excl = incl - run + (wid > 0 ? wsum[wid - 1] : 0);
#pragma unroll
    for (int i = 0; i < 8; i++) g_starts[base + i] = v[i] + excl;
}

// Phase 2: scan the 13 block sums (single warp)
__global__ void scan2_kernel() {
    int lane = threadIdx.x;
    int v = (lane < SCAN_NB) ? g_bsum[lane] : 0;
    int incl = v;
#pragma unroll
    for (int o = 1; o < 16; o <<= 1) {
        int n = __shfl_up_sync(0xffffffffu, incl, o);
        if (lane >= o) incl += n;
    }
    if (lane < SCAN_NB) g_bsum[lane] = incl - v;   // exclusive block offsets
}

// Phase 3: add block offsets, duplicate into cursor
__global__ __launch_bounds__(SCAN_BLK) void scan3_kernel() {
    const int b = blockIdx.x, t = threadIdx.x;
    const int off = g_bsum[b];
    const int base = b * SCAN_EPB + t * 8;
#pragma unroll
    for (int i = 0; i < 8; i++) {
        int s = g_starts[base + i] + off;
        g_starts[base + i] = s;
        g_cursor[base + i] = s;
    }
}

// ---------------------------------------------------------------------------
// Build dest-sorted (src, cls) records
// ---------------------------------------------------------------------------
__global__ void build_kernel(const int* __restrict__ esrc,
                             const int* __restrict__ edst,
                             const int* __restrict__ ecls, int E) {
    int i = blockIdx.x * blockDim.x + threadIdx.x;
    if (i < E) {
        int d = edst[i];
        int pos = atomicAdd(&g_cursor[d], 1);
        g_srccls[pos] = make_int2(esrc[i], ecls[i]);
    }
}

// ---------------------------------------------------------------------------
// Fused dual projection (unchanged from round 1): FFMA GEMM, both W in smem
// ---------------------------------------------------------------------------
#define ROWS_PB 32
#define RPT 16
#define PROJ_SMEM (2 * 128 * 128 * 4 + ROWS_PB * 128 * 4)

__global__ __launch_bounds__(256) void proj_kernel(
    const float* __restrict__ nv, int V,
    const float* __restrict__ Wsrc, const float* __restrict__ bsrc,
    const float* __restrict__ Wdst, const float* __restrict__ bdst)
{
    extern __shared__ float sm[];
    float* Ws = sm;
    float* Wd = sm + 128 * 128;
    float* Xs = sm + 2 * 128 * 128;

    const int tid = threadIdx.x;
    for (int i = tid; i < 128 * 128; i += 256) {
        Ws[i] = Wsrc[i];
        Wd[i] = Wdst[i];
    }
    const int row0 = blockIdx.x * ROWS_PB;
    for (int i = tid; i < ROWS_PB * 128; i += 256) {
        int r = row0 + (i >> 7);
        Xs[i] = (r < V) ? nv[(size_t)r * 128 + (i & 127)] : 0.f;
    }
    __syncthreads();

    const int t = tid & 127;
    const int rbase = (tid >> 7) * RPT;

    float accs[RPT], accd[RPT];
    const float bs = bsrc[t];
    const float bd = bdst[t];
#pragma unroll
    for (int i = 0; i < RPT; i++) { accs[i] = bs; accd[i] = bd; }

    for (int k = 0; k < 128; k += 4) {
        const float ws0 = Ws[(k + 0) * 128 + t];
        const float ws1 = Ws[(k + 1) * 128 + t];
        const float ws2 = Ws[(k + 2) * 128 + t];
        const float ws3 = Ws[(k + 3) * 128 + t];
        const float wd0 = Wd[(k + 0) * 128 + t];
        const float wd1 = Wd[(k + 1) * 128 + t];
        const float wd2 = Wd[(k + 2) * 128 + t];
        const float wd3 = Wd[(k + 3) * 128 + t];
#pragma unroll
        for (int i = 0; i < RPT; i++) {
            float4 x = *reinterpret_cast<const float4*>(&Xs[(rbase + i) * 128 + k]);
            accs[i] = fmaf(x.x, ws0, accs[i]);
            accs[i] = fmaf(x.y, ws1, accs[i]);
            accs[i] = fmaf(x.z, ws2, accs[i]);
            accs[i] = fmaf(x.w, ws3, accs[i]);
            accd[i] = fmaf(x.x, wd0, accd[i]);
            accd[i] = fmaf(x.y, wd1, accd[i]);
            accd[i] = fmaf(x.z, wd2, accd[i]);
            accd[i] = fmaf(x.w, wd3, accd[i]);
        }
    }

#pragma unroll
    for (int i = 0; i < RPT; i++) {
        int r = row0 + rbase + i;
        if (r < V) {
            g_src_proj[(size_t)r * 128 + t]  = accs[i];
            g_dest_proj[(size_t)r * 128 + t] = accd[i];
        }
    }
}

// ---------------------------------------------------------------------------
// Segment-accumulate kernel: one warp per dest node.
// Loads dp[d] once, register-accumulates relu(sp[s]+dp[d]+emb[c]) over the
// dest's edge segment (indices preloaded coalesced, shfl-broadcast, depth-2
// pipelined sp-row gathers), single non-atomic store of out[d].
// ---------------------------------------------------------------------------
__global__ __launch_bounds__(256) void accum_kernel(
    const float* __restrict__ emb, float* __restrict__ out, int V)
{
    __shared__ float4 emb_sm[NTYPES * 32];   // 16 KB
    const int tid = threadIdx.x;
    for (int i = tid; i < NTYPES * 32; i += 256)
        emb_sm[i] = reinterpret_cast<const float4*>(emb)[i];
    __syncthreads();

    const int lane = tid & 31;
    const int d = (blockIdx.x * 256 + tid) >> 5;
    if (d >= V) return;

    const int n    = g_cnt[d];
    const int base = g_starts[d];

    const float4* __restrict__ sp = reinterpret_cast<const float4*>(g_src_proj);
    const float4* __restrict__ dp = reinterpret_cast<const float4*>(g_dest_proj);

    const float4 dv = dp[(size_t)d * 32 + lane];
    float4 acc = make_float4(0.f, 0.f, 0.f, 0.f);

    for (int j0 = 0; j0 < n; j0 += 32) {
        const int m = min(32, n - j0);
        // coalesced index preload: lane j holds edge j0+j's (src, cls)
        int2 sc = make_int2(0, 0);
        if (lane < m) sc = g_srccls[base + j0 + lane];

        // pipelined gather: a = sp row for edge j, an = row for edge j+1
        int s0 = __shfl_sync(0xffffffffu, sc.x, 0);
        float4 a = sp[(size_t)s0 * 32 + lane];

        for (int j = 0; j < m; j++) {
            float4 an = a;
            if (j + 1 < m) {
                int sn = __shfl_sync(0xffffffffu, sc.x, j + 1);
                an = sp[(size_t)sn * 32 + lane];
            }
            const int c = __shfl_sync(0xffffffffu, sc.y, j);
            const float4 e = emb_sm[c * 32 + lane];
            acc.x += fmaxf(a.x + dv.x + e.x, 0.f);
            acc.y += fmaxf(a.y + dv.y + e.y, 0.f);
            acc.z += fmaxf(a.z + dv.z + e.z, 0.f);
            acc.w += fmaxf(a.w + dv.w + e.w, 0.f);
            a = an;
        }
    }

    reinterpret_cast<float4*>(out)[(size_t)d * 32 + lane] = acc;
}

// ---------------------------------------------------------------------------
// Launch. Inputs: node_values, edge_src, edge_dest, edge_cls,
//                 W_src, b_src, W_dest, b_dest, edge_emb
// ---------------------------------------------------------------------------
extern "C" void kernel_launch(void* const* d_in, const int* in_sizes, int n_in,
                              void* d_out, int out_size) {
    const float* nv   = (const float*)d_in[0];
    const int*   esrc = (const int*)  d_in[1];
    const int*   edst = (const int*)  d_in[2];
    const int*   ecls = (const int*)  d_in[3];
    const float* Wsrc = (const float*)d_in[4];
    const float* bsrc = (const float*)d_in[5];
    const float* Wdst = (const float*)d_in[6];
    const float* bdst = (const float*)d_in[7];
    const float* emb  = (const float*)d_in[8];
    float* out = (float*)d_out;

    const int V = in_sizes[0] / DIMV;
    const int E = in_sizes[1];

    cudaFuncSetAttribute(proj_kernel, cudaFuncAttributeMaxDynamicSharedMemorySize,
                         PROJ_SMEM);

    // --- counting sort of edges by dest ---
    zero_cnt_kernel<<<(MAXVP + 255) / 256, 256>>>();
    hist_kernel<<<(E + 255) / 256, 256>>>(edst, E);
    scan1_kernel<<<SCAN_NB, SCAN_BLK>>>();
    scan2_kernel<<<1, 32>>>();
    scan3_kernel<<<SCAN_NB, SCAN_BLK>>>();
    build_kernel<<<(E + 255) / 256, 256>>>(esrc, edst, ecls, E);

    // --- dense dual projection ---
    proj_kernel<<<(V + ROWS_PB - 1) / ROWS_PB, 256, PROJ_SMEM>>>(
        nv, V, Wsrc, bsrc, Wdst, bdst);

    // --- segment accumulate (writes every out row; no zero pass needed) ---
    accum_kernel<<<(V * 32 + 255) / 256, 256>>>(emb, out, V);
}

// round 3
// speedup vs baseline: 1.2940x; 1.2940x over previous
#include <cuda_runtime.h>
#include <cuda_bf16.h>

// Problem constants (shapes fixed by the dataset)
#define DIMV 128
#define NTYPES 32
#define MAXV 50048
#define MAXVP 53248          // 13 * 4096, padded for the scan
#define MAXE 650000

// Scratch (device globals; no allocation allowed)
__device__ float g_src_proj[(size_t)MAXV * DIMV];
__device__ float g_dest_proj[(size_t)MAXV * DIMV];
__device__ int   g_cnt[MAXVP];
__device__ int   g_starts[MAXVP];
__device__ int   g_cursor[MAXVP];
__device__ int   g_bsum[16];
__device__ int2  g_srccls[MAXE];   // (src, cls) sorted by dest

// ---------------------------------------------------------------------------
// Zero the histogram counters
// ---------------------------------------------------------------------------
__global__ void zero_cnt_kernel() {
    int i = blockIdx.x * blockDim.x + threadIdx.x;
    if (i < MAXVP) g_cnt[i] = 0;
}

// ---------------------------------------------------------------------------
// Histogram of edge destinations
// ---------------------------------------------------------------------------
__global__ void hist_kernel(const int* __restrict__ edst, int E) {
    int i = blockIdx.x * blockDim.x + threadIdx.x;
    if (i < E) atomicAdd(&g_cnt[edst[i]], 1);
}

// ---------------------------------------------------------------------------
// 3-phase exclusive scan over g_cnt[MAXVP] -> g_starts, g_cursor
// ---------------------------------------------------------------------------
#define SCAN_BLK 512
#define SCAN_EPB 4096
#define SCAN_NB  (MAXVP / SCAN_EPB)   // 13

__global__ __launch_bounds__(SCAN_BLK) void scan1_kernel() {
    __shared__ int wsum[16];
    const int b = blockIdx.x, t = threadIdx.x;
    const int base = b * SCAN_EPB + t * 8;
    int v[8];
#pragma unroll
    for (int i = 0; i < 8; i++) v[i] = g_cnt[base + i];
    int run = 0;
#pragma unroll
    for (int i = 0; i < 8; i++) { int tmp = v[i]; v[i] = run; run += tmp; }
    int lane = t & 31, wid = t >> 5;
    int incl = run;
#pragma unroll
    for (int o = 1; o < 32; o <<= 1) {
        int n = __shfl_up_sync(0xffffffffu, incl, o);
        if (lane >= o) incl += n;
    }
    if (lane == 31) wsum[wid] = incl;
    __syncthreads();
    if (wid == 0) {
        int ws = (lane < 16) ? wsum[lane] : 0;
#pragma unroll
        for (int o = 1; o < 16; o <<= 1) {
            int n = __shfl_up_sync(0xffffffffu, ws, o);
            if (lane >= o) ws += n;
        }
        if (lane < 16) wsum[lane] = ws;
        if (lane == 15) g_bsum[b] = ws;
    }
    __syncthreads();
    int excl = incl - run + (wid > 0 ? wsum[wid - 1] : 0);
#pragma unroll
    for (int i = 0; i < 8; i++) g_starts[base + i] = v[i] + excl;
}

__global__ void scan2_kernel() {
    int lane = threadIdx.x;
    int v = (lane < SCAN_NB) ? g_bsum[lane] : 0;
    int incl = v;
#pragma unroll
    for (int o = 1; o < 16; o <<= 1) {
        int n = __shfl_up_sync(0xffffffffu, incl, o);
        if (lane >= o) incl += n;
    }
    if (lane < SCAN_NB) g_bsum[lane] = incl - v;
}

__global__ __launch_bounds__(SCAN_BLK) void scan3_kernel() {
    const int b = blockIdx.x, t = threadIdx.x;
    const int off = g_bsum[b];
    const int base = b * SCAN_EPB + t * 8;
#pragma unroll
    for (int i = 0; i < 8; i++) {
        int s = g_starts[base + i] + off;
        g_starts[base + i] = s;
        g_cursor[base + i] = s;
    }
}

// ---------------------------------------------------------------------------
// Build dest-sorted (src, cls) records
// ---------------------------------------------------------------------------
__global__ void build_kernel(const int* __restrict__ esrc,
                             const int* __restrict__ edst,
                             const int* __restrict__ ecls, int E) {
    int i = blockIdx.x * blockDim.x + threadIdx.x;
    if (i < E) {
        int d = edst[i];
        int pos = atomicAdd(&g_cursor[d], 1);
        g_srccls[pos] = make_int2(esrc[i], ecls[i]);
    }
}

// ---------------------------------------------------------------------------
// Fused dual projection: 512 threads, 64 rows/block.
//   t = tid & 127 -> output dim, group = tid >> 7 -> 16-row slice
// 16 warps/SM (4/SMSP) gives 2x issue slack over the FMA-pipe demand.
// Smem: both W (128KB) + 64-row X tile (32KB) = 160KB.
// ---------------------------------------------------------------------------
#define ROWS_PB 64
#define RPT 16
#define PROJ_THREADS 512
#define PROJ_SMEM (2 * 128 * 128 * 4 + ROWS_PB * 128 * 4)

__global__ __launch_bounds__(PROJ_THREADS) void proj_kernel(
    const float* __restrict__ nv, int V,
    const float* __restrict__ Wsrc, const float* __restrict__ bsrc,
    const float* __restrict__ Wdst, const float* __restrict__ bdst)
{
    extern __shared__ float sm[];
    float* Ws = sm;                    // [128][128] row k, col t
    float* Wd = sm + 128 * 128;
    float* Xs = sm + 2 * 128 * 128;    // [64][128]

    const int tid = threadIdx.x;
    for (int i = tid; i < 128 * 128; i += PROJ_THREADS) {
        Ws[i] = Wsrc[i];
        Wd[i] = Wdst[i];
    }
    const int row0 = blockIdx.x * ROWS_PB;
    for (int i = tid; i < ROWS_PB * 128; i += PROJ_THREADS) {
        int r = row0 + (i >> 7);
        Xs[i] = (r < V) ? nv[(size_t)r * 128 + (i & 127)] : 0.f;
    }
    __syncthreads();

    const int t = tid & 127;
    const int rbase = (tid >> 7) * RPT;

    float accs[RPT], accd[RPT];
    const float bs = bsrc[t];
    const float bd = bdst[t];
#pragma unroll
    for (int i = 0; i < RPT; i++) { accs[i] = bs; accd[i] = bd; }

    for (int k = 0; k < 128; k += 4) {
        const float ws0 = Ws[(k + 0) * 128 + t];
        const float ws1 = Ws[(k + 1) * 128 + t];
        const float ws2 = Ws[(k + 2) * 128 + t];
        const float ws3 = Ws[(k + 3) * 128 + t];
        const float wd0 = Wd[(k + 0) * 128 + t];
        const float wd1 = Wd[(k + 1) * 128 + t];
        const float wd2 = Wd[(k + 2) * 128 + t];
        const float wd3 = Wd[(k + 3) * 128 + t];
#pragma unroll
        for (int i = 0; i < RPT; i++) {
            float4 x = *reinterpret_cast<const float4*>(&Xs[(rbase + i) * 128 + k]);
            accs[i] = fmaf(x.x, ws0, accs[i]);
            accs[i] = fmaf(x.y, ws1, accs[i]);
            accs[i] = fmaf(x.z, ws2, accs[i]);
            accs[i] = fmaf(x.w, ws3, accs[i]);
            accd[i] = fmaf(x.x, wd0, accd[i]);
            accd[i] = fmaf(x.y, wd1, accd[i]);
            accd[i] = fmaf(x.z, wd2, accd[i]);
            accd[i] = fmaf(x.w, wd3, accd[i]);
        }
    }

#pragma unroll
    for (int i = 0; i < RPT; i++) {
        int r = row0 + rbase + i;
        if (r < V) {
            g_src_proj[(size_t)r * 128 + t]  = accs[i];
            g_dest_proj[(size_t)r * 128 + t] = accd[i];
        }
    }
}

// ---------------------------------------------------------------------------
// Segment-accumulate: one warp per dest node, register accumulation,
// single non-atomic store. (Unchanged from round 2.)
// ---------------------------------------------------------------------------
__global__ __launch_bounds__(256) void accum_kernel(
    const float* __restrict__ emb, float* __restrict__ out, int V)
{
    __shared__ float4 emb_sm[NTYPES * 32];
    const int tid = threadIdx.x;
    for (int i = tid; i < NTYPES * 32; i += 256)
        emb_sm[i] = reinterpret_cast<const float4*>(emb)[i];
    __syncthreads();

    const int lane = tid & 31;
    const int d = (blockIdx.x * 256 + tid) >> 5;
    if (d >= V) return;

    const int n    = g_cnt[d];
    const int base = g_starts[d];

    const float4* __restrict__ sp = reinterpret_cast<const float4*>(g_src_proj);
    const float4* __restrict__ dp = reinterpret_cast<const float4*>(g_dest_proj);

    const float4 dv = dp[(size_t)d * 32 + lane];
    float4 acc = make_float4(0.f, 0.f, 0.f, 0.f);

    for (int j0 = 0; j0 < n; j0 += 32) {
        const int m = min(32, n - j0);
        int2 sc = make_int2(0, 0);
        if (lane < m) sc = g_srccls[base + j0 + lane];

        int s0 = __shfl_sync(0xffffffffu, sc.x, 0);
        float4 a = sp[(size_t)s0 * 32 + lane];

        for (int j = 0; j < m; j++) {
            float4 an = a;
            if (j + 1 < m) {
                int sn = __shfl_sync(0xffffffffu, sc.x, j + 1);
                an = sp[(size_t)sn * 32 + lane];
            }
            const int c = __shfl_sync(0xffffffffu, sc.y, j);
            const float4 e = emb_sm[c * 32 + lane];
            acc.x += fmaxf(a.x + dv.x + e.x, 0.f);
            acc.y += fmaxf(a.y + dv.y + e.y, 0.f);
            acc.z += fmaxf(a.z + dv.z + e.z, 0.f);
            acc.w += fmaxf(a.w + dv.w + e.w, 0.f);
            a = an;
        }
    }

    reinterpret_cast<float4*>(out)[(size_t)d * 32 + lane] = acc;
}

// ---------------------------------------------------------------------------
// Launch. Inputs: node_values, edge_src, edge_dest, edge_cls,
//                 W_src, b_src, W_dest, b_dest, edge_emb
// NOTE: proj is deliberately launch #3 (0-based) so the ncu -s5 -c1 capture
// (which lands on index 3) profiles it.
// ---------------------------------------------------------------------------
extern "C" void kernel_launch(void* const* d_in, const int* in_sizes, int n_in,
                              void* d_out, int out_size) {
    const float* nv   = (const float*)d_in[0];
    const int*   esrc = (const int*)  d_in[1];
    const int*   edst = (const int*)  d_in[2];
    const int*   ecls = (const int*)  d_in[3];
    const float* Wsrc = (const float*)d_in[4];
    const float* bsrc = (const float*)d_in[5];
    const float* Wdst = (const float*)d_in[6];
    const float* bdst = (const float*)d_in[7];
    const float* emb  = (const float*)d_in[8];
    float* out = (float*)d_out;

    const int V = in_sizes[0] / DIMV;
    const int E = in_sizes[1];

    cudaFuncSetAttribute(proj_kernel, cudaFuncAttributeMaxDynamicSharedMemorySize,
                         PROJ_SMEM);

    // launch index:  0         1     2      3     4      5      6      7
    zero_cnt_kernel<<<(MAXVP + 255) / 256, 256>>>();
    hist_kernel<<<(E + 255) / 256, 256>>>(edst, E);
    scan1_kernel<<<SCAN_NB, SCAN_BLK>>>();
    proj_kernel<<<(V + ROWS_PB - 1) / ROWS_PB, PROJ_THREADS, PROJ_SMEM>>>(
        nv, V, Wsrc, bsrc, Wdst, bdst);                      // independent of scan
    scan2_kernel<<<1, 32>>>();
    scan3_kernel<<<SCAN_NB, SCAN_BLK>>>();
    build_kernel<<<(E + 255) / 256, 256>>>(esrc, edst, ecls, E);
    accum_kernel<<<(V * 32 + 255) / 256, 256>>>(emb, out, V);
}

// round 4
// speedup vs baseline: 1.5812x; 1.2220x over previous
#include <cuda_runtime.h>
#include <cuda_bf16.h>

// Problem constants
#define DIMV 128
#define NTYPES 32
#define MAXV 50048
#define MAXVP 53248
#define MAXE 650000

// Scratch
__device__ float g_src_proj[(size_t)MAXV * DIMV];
__device__ float g_dest_proj[(size_t)MAXV * DIMV];
__device__ int   g_cnt[MAXVP];
__device__ int   g_starts[MAXVP];
__device__ int   g_cursor[MAXVP];
__device__ int   g_bsum[16];
__device__ int2  g_srccls[MAXE];

// Packed fp32x2 helpers (Blackwell FFMA2 — only reachable via PTX)
#define FMA_F32X2(d, a, b, c) \
    asm("fma.rn.f32x2 %0, %1, %2, %3;" : "=l"(d) : "l"(a), "l"(b), "l"(c))
#define PACK2(out, lo, hi) \
    asm("mov.b64 %0, {%1, %2};" : "=l"(out) : "f"(lo), "f"(hi))
#define UNPACK2(lo, hi, in) \
    asm("mov.b64 {%0, %1}, %2;" : "=f"(lo), "=f"(hi) : "l"(in))

// ---------------------------------------------------------------------------
__global__ void zero_cnt_kernel() {
    int i = blockIdx.x * blockDim.x + threadIdx.x;
    if (i < MAXVP) g_cnt[i] = 0;
}

__global__ void hist_kernel(const int* __restrict__ edst, int E) {
    int i = blockIdx.x * blockDim.x + threadIdx.x;
    if (i < E) atomicAdd(&g_cnt[edst[i]], 1);
}

#define SCAN_BLK 512
#define SCAN_EPB 4096
#define SCAN_NB  (MAXVP / SCAN_EPB)   // 13

__global__ __launch_bounds__(SCAN_BLK) void scan1_kernel() {
    __shared__ int wsum[16];
    const int b = blockIdx.x, t = threadIdx.x;
    const int base = b * SCAN_EPB + t * 8;
    int v[8];
#pragma unroll
    for (int i = 0; i < 8; i++) v[i] = g_cnt[base + i];
    int run = 0;
#pragma unroll
    for (int i = 0; i < 8; i++) { int tmp = v[i]; v[i] = run; run += tmp; }
    int lane = t & 31, wid = t >> 5;
    int incl = run;
#pragma unroll
    for (int o = 1; o < 32; o <<= 1) {
        int n = __shfl_up_sync(0xffffffffu, incl, o);
        if (lane >= o) incl += n;
    }
    if (lane == 31) wsum[wid] = incl;
    __syncthreads();
    if (wid == 0) {
        int ws = (lane < 16) ? wsum[lane] : 0;
#pragma unroll
        for (int o = 1; o < 16; o <<= 1) {
            int n = __shfl_up_sync(0xffffffffu, ws, o);
            if (lane >= o) ws += n;
        }
        if (lane < 16) wsum[lane] = ws;
        if (lane == 15) g_bsum[b] = ws;
    }
    __syncthreads();
    int excl = incl - run + (wid > 0 ? wsum[wid - 1] : 0);
#pragma unroll
    for (int i = 0; i < 8; i++) g_starts[base + i] = v[i] + excl;
}

__global__ void scan2_kernel() {
    int lane = threadIdx.x;
    int v = (lane < SCAN_NB) ? g_bsum[lane] : 0;
    int incl = v;
#pragma unroll
    for (int o = 1; o < 16; o <<= 1) {
        int n = __shfl_up_sync(0xffffffffu, incl, o);
        if (lane >= o) incl += n;
    }
    if (lane < SCAN_NB) g_bsum[lane] = incl - v;
}

__global__ __launch_bounds__(SCAN_BLK) void scan3_kernel() {
    const int b = blockIdx.x, t = threadIdx.x;
    const int off = g_bsum[b];
    const int base = b * SCAN_EPB + t * 8;
#pragma unroll
    for (int i = 0; i < 8; i++) {
        int s = g_starts[base + i] + off;
        g_starts[base + i] = s;
        g_cursor[base + i] = s;
    }
}

__global__ void build_kernel(const int* __restrict__ esrc,
                             const int* __restrict__ edst,
                             const int* __restrict__ ecls, int E) {
    int i = blockIdx.x * blockDim.x + threadIdx.x;
    if (i < E) {
        int d = edst[i];
        int pos = atomicAdd(&g_cursor[d], 1);
        g_srccls[pos] = make_int2(esrc[i], ecls[i]);
    }
}

// ---------------------------------------------------------------------------
// Projection GEMM, register-tiled with packed f32x2 FMAs.
// Block: 64 rows x 128 cols (one weight matrix, chosen by blockIdx.y).
// 128 threads, 8x8 thread tile (rows x cols), acc as 8x4 f32x2.
// Smem: X^T [128][64] (32KB) + W [128][128] (64KB) = 96KB -> 2 blocks/SM.
// Lane map: 4 row-groups x 8 col-groups -> both LDS.128 streams 1-phase.
// ---------------------------------------------------------------------------
#define GROWS 64
#define PROJ2_SMEM ((128 * 64 + 128 * 128) * 4)

__global__ __launch_bounds__(128, 2) void proj_kernel(
    const float* __restrict__ nv, int V,
    const float* __restrict__ Wsrc, const float* __restrict__ bsrc,
    const float* __restrict__ Wdst, const float* __restrict__ bdst)
{
    extern __shared__ float sm[];
    float* Xs = sm;              // [k][r] transposed, 128 x 64
    float* Wsm = sm + 128 * 64;  // [k][n], 128 x 128

    const float* __restrict__ W = blockIdx.y ? Wdst : Wsrc;
    const float* __restrict__ bias = blockIdx.y ? bdst : bsrc;
    float* __restrict__ outp = blockIdx.y ? g_dest_proj : g_src_proj;

    const int tid = threadIdx.x;
    const int row0 = blockIdx.x * GROWS;

    // Load W [128][128] coalesced (float4)
    {
        const float4* W4 = reinterpret_cast<const float4*>(W);
        float4* Wsm4 = reinterpret_cast<float4*>(Wsm);
        for (int i = tid; i < 128 * 32; i += 128) Wsm4[i] = W4[i];
    }
    // Load X transposed: idx -> (k4, r); lanes contiguous in r so smem
    // writes are conflict-free; gmem reads are 16B/lane (L1-friendly).
    {
        const float4* nv4 = reinterpret_cast<const float4*>(nv);
        for (int idx = tid; idx < 32 * GROWS; idx += 128) {
            int r = idx & (GROWS - 1);
            int k4 = idx >> 6;
            int gr = row0 + r;
            float4 v = make_float4(0.f, 0.f, 0.f, 0.f);
            if (gr < V) v = nv4[(size_t)gr * 32 + k4];
            Xs[(k4 * 4 + 0) * GROWS + r] = v.x;
            Xs[(k4 * 4 + 1) * GROWS + r] = v.y;
            Xs[(k4 * 4 + 2) * GROWS + r] = v.z;
            Xs[(k4 * 4 + 3) * GROWS + r] = v.w;
        }
    }
    __syncthreads();

    const int wid = tid >> 5, lane = tid & 31;
    const int tm = ((wid >> 1) << 2) + (lane >> 3);   // 0..7  row group
    const int tn = ((wid & 1) << 3) + (lane & 7);     // 0..15 col group
    const int abase = tm * 8;
    const int bbase = tn * 8;

    // Accumulators initialized with bias pairs
    unsigned long long acc[8][4];
    {
        unsigned long long bp[4];
#pragma unroll
        for (int j = 0; j < 4; j++)
            PACK2(bp[j], bias[bbase + 2 * j], bias[bbase + 2 * j + 1]);
#pragma unroll
        for (int i = 0; i < 8; i++)
#pragma unroll
            for (int j = 0; j < 4; j++) acc[i][j] = bp[j];
    }

#pragma unroll 4
    for (int k = 0; k < 128; k++) {
        float4 a0 = *reinterpret_cast<const float4*>(&Xs[k * GROWS + abase]);
        float4 a1 = *reinterpret_cast<const float4*>(&Xs[k * GROWS + abase + 4]);
        float4 b0 = *reinterpret_cast<const float4*>(&Wsm[k * 128 + bbase]);
        float4 b1 = *reinterpret_cast<const float4*>(&Wsm[k * 128 + bbase + 4]);

        unsigned long long bb[4];
        PACK2(bb[0], b0.x, b0.y);
        PACK2(bb[1], b0.z, b0.w);
        PACK2(bb[2], b1.x, b1.y);
        PACK2(bb[3], b1.z, b1.w);

        unsigned long long aa[8];
        PACK2(aa[0], a0.x, a0.x);
        PACK2(aa[1], a0.y, a0.y);
        PACK2(aa[2], a0.z, a0.z);
        PACK2(aa[3], a0.w, a0.w);
        PACK2(aa[4], a1.x, a1.x);
        PACK2(aa[5], a1.y, a1.y);
        PACK2(aa[6], a1.z, a1.z);
        PACK2(aa[7], a1.w, a1.w);

#pragma unroll
        for (int i = 0; i < 8; i++)
#pragma unroll
            for (int j = 0; j < 4; j++)
                FMA_F32X2(acc[i][j], aa[i], bb[j], acc[i][j]);
    }

    // Store 8 rows x 8 cols as 2 float4 per row
#pragma unroll
    for (int i = 0; i < 8; i++) {
        int r = row0 + abase + i;
        if (r < V) {
            float4 o0, o1;
            UNPACK2(o0.x, o0.y, acc[i][0]);
            UNPACK2(o0.z, o0.w, acc[i][1]);
            UNPACK2(o1.x, o1.y, acc[i][2]);
            UNPACK2(o1.z, o1.w, acc[i][3]);
            float4* op = reinterpret_cast<float4*>(&outp[(size_t)r * 128 + bbase]);
            op[0] = o0;
            op[1] = o1;
        }
    }
}

// ---------------------------------------------------------------------------
// Segment-accumulate: one warp per dest node (unchanged).
// ---------------------------------------------------------------------------
__global__ __launch_bounds__(256) void accum_kernel(
    const float* __restrict__ emb, float* __restrict__ out, int V)
{
    __shared__ float4 emb_sm[NTYPES * 32];
    const int tid = threadIdx.x;
    for (int i = tid; i < NTYPES * 32; i += 256)
        emb_sm[i] = reinterpret_cast<const float4*>(emb)[i];
    __syncthreads();

    const int lane = tid & 31;
    const int d = (blockIdx.x * 256 + tid) >> 5;
    if (d >= V) return;

    const int n    = g_cnt[d];
    const int base = g_starts[d];

    const float4* __restrict__ sp = reinterpret_cast<const float4*>(g_src_proj);
    const float4* __restrict__ dp = reinterpret_cast<const float4*>(g_dest_proj);

    const float4 dv = dp[(size_t)d * 32 + lane];
    float4 acc = make_float4(0.f, 0.f, 0.f, 0.f);

    for (int j0 = 0; j0 < n; j0 += 32) {
        const int m = min(32, n - j0);
        int2 sc = make_int2(0, 0);
        if (lane < m) sc = g_srccls[base + j0 + lane];

        int s0 = __shfl_sync(0xffffffffu, sc.x, 0);
        float4 a = sp[(size_t)s0 * 32 + lane];

        for (int j = 0; j < m; j++) {
            float4 an = a;
            if (j + 1 < m) {
                int sn = __shfl_sync(0xffffffffu, sc.x, j + 1);
                an = sp[(size_t)sn * 32 + lane];
            }
            const int c = __shfl_sync(0xffffffffu, sc.y, j);
            const float4 e = emb_sm[c * 32 + lane];
            acc.x += fmaxf(a.x + dv.x + e.x, 0.f);
            acc.y += fmaxf(a.y + dv.y + e.y, 0.f);
            acc.z += fmaxf(a.z + dv.z + e.z, 0.f);
            acc.w += fmaxf(a.w + dv.w + e.w, 0.f);
            a = an;
        }
    }

    reinterpret_cast<float4*>(out)[(size_t)d * 32 + lane] = acc;
}

// ---------------------------------------------------------------------------
// Launch. proj stays at launch index 3 so ncu profiles it.
// ---------------------------------------------------------------------------
extern "C" void kernel_launch(void* const* d_in, const int* in_sizes, int n_in,
                              void* d_out, int out_size) {
    const float* nv   = (const float*)d_in[0];
    const int*   esrc = (const int*)  d_in[1];
    const int*   edst = (const int*)  d_in[2];
    const int*   ecls = (const int*)  d_in[3];
    const float* Wsrc = (const float*)d_in[4];
    const float* bsrc = (const float*)d_in[5];
    const float* Wdst = (const float*)d_in[6];
    const float* bdst = (const float*)d_in[7];
    const float* emb  = (const float*)d_in[8];
    float* out = (float*)d_out;

    const int V = in_sizes[0] / DIMV;
    const int E = in_sizes[1];

    cudaFuncSetAttribute(proj_kernel, cudaFuncAttributeMaxDynamicSharedMemorySize,
                         PROJ2_SMEM);

    zero_cnt_kernel<<<(MAXVP + 255) / 256, 256>>>();                  // 0
    hist_kernel<<<(E + 255) / 256, 256>>>(edst, E);                   // 1
    scan1_kernel<<<SCAN_NB, SCAN_BLK>>>();                            // 2
    {
        dim3 grid((V + GROWS - 1) / GROWS, 2);
        proj_kernel<<<grid, 128, PROJ2_SMEM>>>(nv, V, Wsrc, bsrc, Wdst, bdst); // 3
    }
    scan2_kernel<<<1, 32>>>();                                        // 4
    scan3_kernel<<<SCAN_NB, SCAN_BLK>>>();                            // 5
    build_kernel<<<(E + 255) / 256, 256>>>(esrc, edst, ecls, E);      // 6
    accum_kernel<<<(V * 32 + 255) / 256, 256>>>(emb, out, V);         // 7
}

// round 5
// speedup vs baseline: 1.9985x; 1.2639x over previous
#include <cuda_runtime.h>
#include <cuda_bf16.h>
#include <cstring>

// Problem constants
#define DIMV 128
#define NTYPES 32
#define MAXV 50048
#define MAXVP 53248
#define MAXE 650000

// Scratch
__device__ float g_src_proj[(size_t)MAXV * DIMV];
__device__ float g_dest_proj[(size_t)MAXV * DIMV];
__device__ int   g_cnt[MAXVP];
__device__ int   g_starts[MAXVP];
__device__ int   g_cursor[MAXVP];
__device__ int   g_bsum[16];
__device__ int2  g_srccls[MAXE];

// ---------------------------------------------------------------------------
__global__ void zero_cnt_kernel() {
    int i = blockIdx.x * blockDim.x + threadIdx.x;
    if (i < MAXVP) g_cnt[i] = 0;
}

__global__ void hist_kernel(const int* __restrict__ edst, int E) {
    int i = blockIdx.x * blockDim.x + threadIdx.x;
    if (i < E) atomicAdd(&g_cnt[edst[i]], 1);
}

#define SCAN_BLK 512
#define SCAN_EPB 4096
#define SCAN_NB  (MAXVP / SCAN_EPB)   // 13

__global__ __launch_bounds__(SCAN_BLK) void scan1_kernel() {
    __shared__ int wsum[16];
    const int b = blockIdx.x, t = threadIdx.x;
    const int base = b * SCAN_EPB + t * 8;
    int v[8];
#pragma unroll
    for (int i = 0; i < 8; i++) v[i] = g_cnt[base + i];
    int run = 0;
#pragma unroll
    for (int i = 0; i < 8; i++) { int tmp = v[i]; v[i] = run; run += tmp; }
    int lane = t & 31, wid = t >> 5;
    int incl = run;
#pragma unroll
    for (int o = 1; o < 32; o <<= 1) {
        int n = __shfl_up_sync(0xffffffffu, incl, o);
        if (lane >= o) incl += n;
    }
    if (lane == 31) wsum[wid] = incl;
    __syncthreads();
    if (wid == 0) {
        int ws = (lane < 16) ? wsum[lane] : 0;
#pragma unroll
        for (int o = 1; o < 16; o <<= 1) {
            int n = __shfl_up_sync(0xffffffffu, ws, o);
            if (lane >= o) ws += n;
        }
        if (lane < 16) wsum[lane] = ws;
        if (lane == 15) g_bsum[b] = ws;
    }
    __syncthreads();
    int excl = incl - run + (wid > 0 ? wsum[wid - 1] : 0);
#pragma unroll
    for (int i = 0; i < 8; i++) g_starts[base + i] = v[i] + excl;
}

__global__ void scan2_kernel() {
    int lane = threadIdx.x;
    int v = (lane < SCAN_NB) ? g_bsum[lane] : 0;
    int incl = v;
#pragma unroll
    for (int o = 1; o < 16; o <<= 1) {
        int n = __shfl_up_sync(0xffffffffu, incl, o);
        if (lane >= o) incl += n;
    }
    if (lane < SCAN_NB) g_bsum[lane] = incl - v;
}

__global__ __launch_bounds__(SCAN_BLK) void scan3_kernel() {
    const int b = blockIdx.x, t = threadIdx.x;
    const int off = g_bsum[b];
    const int base = b * SCAN_EPB + t * 8;
#pragma unroll
    for (int i = 0; i < 8; i++) {
        int s = g_starts[base + i] + off;
        g_starts[base + i] = s;
        g_cursor[base + i] = s;
    }
}

__global__ void build_kernel(const int* __restrict__ esrc,
                             const int* __restrict__ edst,
                             const int* __restrict__ ecls, int E) {
    int i = blockIdx.x * blockDim.x + threadIdx.x;
    if (i < E) {
        int d = edst[i];
        int pos = atomicAdd(&g_cursor[d], 1);
        g_srccls[pos] = make_int2(esrc[i], ecls[i]);
    }
}

// ---------------------------------------------------------------------------
// Tensor-core projection with bf16 hi/lo split (error ~2^-16).
// CTA: 128 rows x 128 cols x K=128, BOTH weight matrices.
// Smem layout (bf16, rows padded to 144B for conflict-free ldmatrix):
//   A_hi  [kHalf][128 rows][64+8]   2*18432 = 36864
//   A_lo  same                       36864
//   W[m]  hi [nHalf][128 k][64+8] 36864 ; lo 36864  (m = src, dest)
// Total 221184 B. 256 threads, warp grid 4(M) x 2(N), warp tile 32x64.
// ---------------------------------------------------------------------------
#define TROWS 128
#define HBUF  18432                 // one half-buffer: 128 * 144
#define A_HI  0
#define A_LO  36864
#define W_OFF 73728                 // per matrix: hi 36864 + lo 36864
#define PROJ_SMEM 221184

#define LDSM4(r0, r1, r2, r3, addr) \
    asm volatile("ldmatrix.sync.aligned.m8n8.x4.shared.b16 {%0,%1,%2,%3}, [%4];" \
        : "=r"(r0), "=r"(r1), "=r"(r2), "=r"(r3) : "r"(addr))

#define LDSM4T(r0, r1, r2, r3, addr) \
    asm volatile("ldmatrix.sync.aligned.m8n8.x4.trans.shared.b16 {%0,%1,%2,%3}, [%4];" \
        : "=r"(r0), "=r"(r1), "=r"(r2), "=r"(r3) : "r"(addr))

#define MMA16816(d, a, b0, b1) \
    asm volatile("mma.sync.aligned.m16n8k16.row.col.f32.bf16.bf16.f32 " \
        "{%0,%1,%2,%3}, {%4,%5,%6,%7}, {%8,%9}, {%0,%1,%2,%3};" \
        : "+f"(d[0]), "+f"(d[1]), "+f"(d[2]), "+f"(d[3]) \
        : "r"(a[0]), "r"(a[1]), "r"(a[2]), "r"(a[3]), "r"(b0), "r"(b1))

__device__ __forceinline__ unsigned pack_bf2(__nv_bfloat16 a, __nv_bfloat16 b) {
    __nv_bfloat162 t = __halves2bfloat162(a, b);
    unsigned u;
    memcpy(&u, &t, 4);
    return u;
}

// split x into bf16 hi + bf16 lo (residual)
__device__ __forceinline__ void split_bf(float x, __nv_bfloat16& h, __nv_bfloat16& l) {
    h = __float2bfloat16_rn(x);
    l = __float2bfloat16_rn(x - __bfloat162float(h));
}

__global__ __launch_bounds__(256, 1) void proj_kernel(
    const float* __restrict__ nv, int V,
    const float* __restrict__ Wsrc, const float* __restrict__ bsrc,
    const float* __restrict__ Wdst, const float* __restrict__ bdst)
{
    extern __shared__ __align__(16) char smem[];
    unsigned smemu;
    asm("{ .reg .u64 t; cvta.to.shared.u64 t, %1; cvt.u32.u64 %0, t; }"
        : "=r"(smemu) : "l"(smem));

    const int tid = threadIdx.x;
    const int row0 = blockIdx.x * TROWS;

    // ---- stage + convert A (node rows) ----
    {
        const float4* nv4 = reinterpret_cast<const float4*>(nv);
        for (int idx = tid; idx < TROWS * 32; idx += 256) {
            int r = idx >> 5, q = idx & 31;
            int kk = q * 4, h = kk >> 6, kl = kk & 63;
            int gr = row0 + r;
            float4 v = make_float4(0.f, 0.f, 0.f, 0.f);
            if (gr < V) v = nv4[(size_t)gr * 32 + q];
            __nv_bfloat16 h0, h1, h2, h3, l0, l1, l2, l3;
            split_bf(v.x, h0, l0); split_bf(v.y, h1, l1);
            split_bf(v.z, h2, l2); split_bf(v.w, h3, l3);
            size_t off = (size_t)h * HBUF + r * 144 + kl * 2;
            *reinterpret_cast<uint2*>(smem + A_HI + off) =
                make_uint2(pack_bf2(h0, h1), pack_bf2(h2, h3));
            *reinterpret_cast<uint2*>(smem + A_LO + off) =
                make_uint2(pack_bf2(l0, l1), pack_bf2(l2, l3));
        }
    }
    // ---- stage + convert both W (K-major, rows = k) ----
    for (int m = 0; m < 2; m++) {
        const float4* W4 = reinterpret_cast<const float4*>(m ? Wdst : Wsrc);
        char* wb = smem + W_OFF + m * 73728;
        for (int idx = tid; idx < 128 * 32; idx += 256) {
            int k = idx >> 5, q = idx & 31;
            int n = q * 4, h = n >> 6, nl = n & 63;
            float4 v = W4[idx];
            __nv_bfloat16 h0, h1, h2, h3, l0, l1, l2, l3;
            split_bf(v.x, h0, l0); split_bf(v.y, h1, l1);
            split_bf(v.z, h2, l2); split_bf(v.w, h3, l3);
            size_t off = (size_t)h * HBUF + k * 144 + nl * 2;
            *reinterpret_cast<uint2*>(wb + off) =
                make_uint2(pack_bf2(h0, h1), pack_bf2(h2, h3));
            *reinterpret_cast<uint2*>(wb + 36864 + off) =
                make_uint2(pack_bf2(l0, l1), pack_bf2(l2, l3));
        }
    }
    __syncthreads();

    const int lane = tid & 31, wid = tid >> 5;
    const int warp_m = wid >> 1;          // 0..3 : 32-row slice
    const int warp_n = wid & 1;           // 0..1 : 64-col half
    const int sel = lane >> 3, li = lane & 7;

    for (int wSel = 0; wSel < 2; wSel++) {
        const float* __restrict__ bias = wSel ? bdst : bsrc;
        float* __restrict__ outp = wSel ? g_dest_proj : g_src_proj;
        const unsigned wHiB = smemu + W_OFF + wSel * 73728 + warp_n * HBUF;

        float acc[2][8][4];
#pragma unroll
        for (int j = 0; j < 8; j++) {
            int col = warp_n * 64 + j * 8 + (lane & 3) * 2;
            float b0 = bias[col], b1 = bias[col + 1];
#pragma unroll
            for (int m = 0; m < 2; m++) {
                acc[m][j][0] = b0; acc[m][j][1] = b1;
                acc[m][j][2] = b0; acc[m][j][3] = b1;
            }
        }

#pragma unroll
        for (int h = 0; h < 2; h++) {
#pragma unroll
            for (int kf = 0; kf < 4; kf++) {
                // A fragments (hi & lo) for both m16 tiles
                unsigned ah[2][4], al[2][4];
                {
                    int arow = warp_m * 32 + li + (sel & 1) * 8;
                    int kch = kf * 16 + (sel >> 1) * 8;
                    unsigned a0 = smemu + A_HI + h * HBUF + arow * 144 + kch * 2;
                    LDSM4(ah[0][0], ah[0][1], ah[0][2], ah[0][3], a0);
                    LDSM4(ah[1][0], ah[1][1], ah[1][2], ah[1][3], a0 + 16 * 144);
                    unsigned a1 = a0 + (A_LO - A_HI);
                    LDSM4(al[0][0], al[0][1], al[0][2], al[0][3], a1);
                    LDSM4(al[1][0], al[1][1], al[1][2], al[1][3], a1 + 16 * 144);
                }
                const int krow = h * 64 + kf * 16 + li + (sel & 1) * 8;
#pragma unroll
                for (int jj = 0; jj < 4; jj++) {
                    unsigned bh[4], bl[4];
                    int nch = jj * 16 + (sel >> 1) * 8;
                    unsigned boff = wHiB + krow * 144 + nch * 2;
                    LDSM4T(bh[0], bh[1], bh[2], bh[3], boff);
                    LDSM4T(bl[0], bl[1], bl[2], bl[3], boff + 36864);
                    // hi*hi
#pragma unroll
                    for (int m = 0; m < 2; m++) {
                        MMA16816(acc[m][2 * jj + 0], ah[m], bh[0], bh[1]);
                        MMA16816(acc[m][2 * jj + 1], ah[m], bh[2], bh[3]);
                    }
                    // hi*lo
#pragma unroll
                    for (int m = 0; m < 2; m++) {
                        MMA16816(acc[m][2 * jj + 0], ah[m], bl[0], bl[1]);
                        MMA16816(acc[m][2 * jj + 1], ah[m], bl[2], bl[3]);
                    }
                    // lo*hi
#pragma unroll
                    for (int m = 0; m < 2; m++) {
                        MMA16816(acc[m][2 * jj + 0], al[m], bh[0], bh[1]);
                        MMA16816(acc[m][2 * jj + 1], al[m], bh[2], bh[3]);
                    }
                }
            }
        }

        // epilogue: direct global stores (v2)
#pragma unroll
        for (int m = 0; m < 2; m++) {
            int rlo = row0 + warp_m * 32 + m * 16 + (lane >> 2);
#pragma unroll
            for (int j = 0; j < 8; j++) {
                int col = warp_n * 64 + j * 8 + (lane & 3) * 2;
                if (rlo < V)
                    *reinterpret_cast<float2*>(&outp[(size_t)rlo * 128 + col]) =
                        make_float2(acc[m][j][0], acc[m][j][1]);
                int rhi = rlo + 8;
                if (rhi < V)
                    *reinterpret_cast<float2*>(&outp[(size_t)rhi * 128 + col]) =
                        make_float2(acc[m][j][2], acc[m][j][3]);
            }
        }
    }
}

// ---------------------------------------------------------------------------
// Segment-accumulate: one warp per dest node (unchanged).
// ---------------------------------------------------------------------------
__global__ __launch_bounds__(256) void accum_kernel(
    const float* __restrict__ emb, float* __restrict__ out, int V)
{
    __shared__ float4 emb_sm[NTYPES * 32];
    const int tid = threadIdx.x;
    for (int i = tid; i < NTYPES * 32; i += 256)
        emb_sm[i] = reinterpret_cast<const float4*>(emb)[i];
    __syncthreads();

    const int lane = tid & 31;
    const int d = (blockIdx.x * 256 + tid) >> 5;
    if (d >= V) return;

    const int n    = g_cnt[d];
    const int base = g_starts[d];

    const float4* __restrict__ sp = reinterpret_cast<const float4*>(g_src_proj);
    const float4* __restrict__ dp = reinterpret_cast<const float4*>(g_dest_proj);

    const float4 dv = dp[(size_t)d * 32 + lane];
    float4 acc = make_float4(0.f, 0.f, 0.f, 0.f);

    for (int j0 = 0; j0 < n; j0 += 32) {
        const int m = min(32, n - j0);
        int2 sc = make_int2(0, 0);
        if (lane < m) sc = g_srccls[base + j0 + lane];

        int s0 = __shfl_sync(0xffffffffu, sc.x, 0);
        float4 a = sp[(size_t)s0 * 32 + lane];

        for (int j = 0; j < m; j++) {
            float4 an = a;
            if (j + 1 < m) {
                int sn = __shfl_sync(0xffffffffu, sc.x, j + 1);
                an = sp[(size_t)sn * 32 + lane];
            }
            const int c = __shfl_sync(0xffffffffu, sc.y, j);
            const float4 e = emb_sm[c * 32 + lane];
            acc.x += fmaxf(a.x + dv.x + e.x, 0.f);
            acc.y += fmaxf(a.y + dv.y + e.y, 0.f);
            acc.z += fmaxf(a.z + dv.z + e.z, 0.f);
            acc.w += fmaxf(a.w + dv.w + e.w, 0.f);
            a = an;
        }
    }

    reinterpret_cast<float4*>(out)[(size_t)d * 32 + lane] = acc;
}

// ---------------------------------------------------------------------------
// Launch. proj stays at index 3 (ncu profiles launch #3).
// ---------------------------------------------------------------------------
extern "C" void kernel_launch(void* const* d_in, const int* in_sizes, int n_in,
                              void* d_out, int out_size) {
    const float* nv   = (const float*)d_in[0];
    const int*   esrc = (const int*)  d_in[1];
    const int*   edst = (const int*)  d_in[2];
    const int*   ecls = (const int*)  d_in[3];
    const float* Wsrc = (const float*)d_in[4];
    const float* bsrc = (const float*)d_in[5];
    const float* Wdst = (const float*)d_in[6];
    const float* bdst = (const float*)d_in[7];
    const float* emb  = (const float*)d_in[8];
    float* out = (float*)d_out;

    const int V = in_sizes[0] / DIMV;
    const int E = in_sizes[1];

    cudaFuncSetAttribute(proj_kernel, cudaFuncAttributeMaxDynamicSharedMemorySize,
                         PROJ_SMEM);

    zero_cnt_kernel<<<(MAXVP + 255) / 256, 256>>>();                  // 0
    hist_kernel<<<(E + 255) / 256, 256>>>(edst, E);                   // 1
    scan1_kernel<<<SCAN_NB, SCAN_BLK>>>();                            // 2
    proj_kernel<<<(V + TROWS - 1) / TROWS, 256, PROJ_SMEM>>>(
        nv, V, Wsrc, bsrc, Wdst, bdst);                               // 3
    scan2_kernel<<<1, 32>>>();                                        // 4
    scan3_kernel<<<SCAN_NB, SCAN_BLK>>>();                            // 5
    build_kernel<<<(E + 255) / 256, 256>>>(esrc, edst, ecls, E);      // 6
    accum_kernel<<<(V * 32 + 255) / 256, 256>>>(emb, out, V);         // 7
}